// round 5
// baseline (speedup 1.0000x reference)
#include <cuda_runtime.h>
#include <cuda_bf16.h>
#include <math.h>

// Problem constants
#define NB 8        // batch
#define C 256       // channels
#define HW 1024     // 32*32
#define NH 32       // heads
#define HD 8        // head dim
#define NG 8        // groupnorm groups
#define CG 32       // channels per group
#define GN_EPS 1e-5f

// Scratch (allocation-free rule: __device__ globals)
__device__ float g_qkv[(size_t)NB * 3 * C * HW];   // 24 MB
__device__ float g_y[(size_t)NB * C * HW];         // 8 MB
__device__ float g_A[NB * C];                      // per-(n,c) GN scale
__device__ float g_B[NB * C];                      // per-(n,c) GN shift

typedef unsigned long long ull;

// ---------------------------------------------------------------------------
// Packed f32x2 helpers (sm_103a FFMA2 path)
// ---------------------------------------------------------------------------
__device__ __forceinline__ ull pack2(float lo, float hi) {
    ull r;
    asm("mov.b64 %0, {%1, %2};" : "=l"(r) : "f"(lo), "f"(hi));
    return r;
}
__device__ __forceinline__ void unpack2(ull p, float& lo, float& hi) {
    asm("mov.b64 {%0, %1}, %2;" : "=f"(lo), "=f"(hi) : "l"(p));
}
__device__ __forceinline__ ull ffma2(ull a, ull b, ull c) {
    ull d;
    asm("fma.rn.f32x2 %0, %1, %2, %3;" : "=l"(d) : "l"(a), "l"(b), "l"(c));
    return d;
}
__device__ __forceinline__ ull fadd2(ull a, ull b) {
    ull d;
    asm("add.rn.f32x2 %0, %1, %2;" : "=l"(d) : "l"(a), "l"(b));
    return d;
}
__device__ __forceinline__ float ex2f(float x) {
    float y;
    asm("ex2.approx.f32 %0, %1;" : "=f"(y) : "f"(x));
    return y;
}

// ---------------------------------------------------------------------------
// Kernel 1: GroupNorm stats only.  One CTA per (n, group).
// Emits per-channel affine:  A[n,c] = gn_w[c]*rstd,  B[n,c] = gn_b[c]-mu*A.
// Normalization itself is fused into the QKV GEMM loader.
// ---------------------------------------------------------------------------
__global__ void gn_stats_kernel(const float* __restrict__ x,
                                const float* __restrict__ w,
                                const float* __restrict__ b,
                                float* __restrict__ A,
                                float* __restrict__ B)
{
    const int n = blockIdx.x >> 3;
    const int g = blockIdx.x & 7;
    const size_t base = ((size_t)n * NG + g) * (CG * HW);
    const float4* xp = (const float4*)(x + base);

    float s = 0.f, ss = 0.f;
    for (int i = threadIdx.x; i < (CG * HW) / 4; i += 256) {
        float4 v = xp[i];
        s  += v.x + v.y + v.z + v.w;
        ss += v.x * v.x + v.y * v.y + v.z * v.z + v.w * v.w;
    }
    for (int o = 16; o > 0; o >>= 1) {
        s  += __shfl_xor_sync(0xffffffffu, s, o);
        ss += __shfl_xor_sync(0xffffffffu, ss, o);
    }
    __shared__ float rs[8], rss[8];
    __shared__ float s_mu, s_rstd;
    const int warp = threadIdx.x >> 5, lane = threadIdx.x & 31;
    if (lane == 0) { rs[warp] = s; rss[warp] = ss; }
    __syncthreads();
    if (threadIdx.x == 0) {
        float ts = 0.f, tss = 0.f;
        #pragma unroll
        for (int i = 0; i < 8; i++) { ts += rs[i]; tss += rss[i]; }
        const float inv_n = 1.0f / (CG * HW);
        float mu = ts * inv_n;
        float var = tss * inv_n - mu * mu;
        s_mu = mu;
        s_rstd = rsqrtf(var + GN_EPS);
    }
    __syncthreads();
    if (threadIdx.x < CG) {
        const int c = (g << 5) + threadIdx.x;
        const float a = w[c] * s_rstd;
        A[n * C + c] = a;
        B[n * C + c] = fmaf(-s_mu, a, b[c]);
    }
}

// ---------------------------------------------------------------------------
// Kernel 2/4: batched GEMM  Out[n][o][t] = sum_c W[o][c] * Xn[c][t] + bias[o]
// where Xn = Ac[c]*X[c][t] + Bc[c] if Ac != null (fused GroupNorm), else X.
// tile 128(o) x 64(t) x 16(k), 256 threads, 8x4 outputs per thread, f32x2.
// ---------------------------------------------------------------------------
__global__ void gemm_kernel(const float* __restrict__ W,
                            const float* __restrict__ X,
                            const float* __restrict__ bias,
                            const float* __restrict__ resid,
                            const float* __restrict__ Ac,   // nullable: GN scale
                            const float* __restrict__ Bc,   // nullable: GN shift
                            float* __restrict__ Out,
                            int M)
{
    const int n  = blockIdx.x;
    const int o0 = blockIdx.y * 128;
    const int t0 = blockIdx.z * 64;

    __shared__ float Ws[2][16][132];
    __shared__ float Xs[2][16][64];

    const int tid = threadIdx.x;
    const int tx = tid & 15, ty = tid >> 4;
    const int ty8 = ty * 8, tx4 = tx * 4;

    ull acc2[8][2];
    #pragma unroll
    for (int i = 0; i < 8; i++) { acc2[i][0] = 0ull; acc2[i][1] = 0ull; }

    const int wrow = tid >> 1;
    const int wcol = (tid & 1) << 3;
    const int xrow = tid >> 4, xcol = (tid & 15) << 2;

    const float* Wp = W + (size_t)(o0 + wrow) * C + wcol;
    const float* Xp = X + ((size_t)n * C + xrow) * HW + t0 + xcol;
    const float* Ap = Ac ? (Ac + n * C + xrow) : nullptr;
    const float* Bp = Bc ? (Bc + n * C + xrow) : nullptr;

    float4 wv0 = *(const float4*)Wp;
    float4 wv1 = *(const float4*)(Wp + 4);
    float4 xv  = *(const float4*)Xp;
    if (Ap) {
        const float a = Ap[0], bb = Bp[0];
        xv.x = fmaf(xv.x, a, bb); xv.y = fmaf(xv.y, a, bb);
        xv.z = fmaf(xv.z, a, bb); xv.w = fmaf(xv.w, a, bb);
    }

    int buf = 0;
    for (int k0 = 0; k0 < C; k0 += 16) {
        Ws[buf][wcol + 0][wrow] = wv0.x;
        Ws[buf][wcol + 1][wrow] = wv0.y;
        Ws[buf][wcol + 2][wrow] = wv0.z;
        Ws[buf][wcol + 3][wrow] = wv0.w;
        Ws[buf][wcol + 4][wrow] = wv1.x;
        Ws[buf][wcol + 5][wrow] = wv1.y;
        Ws[buf][wcol + 6][wrow] = wv1.z;
        Ws[buf][wcol + 7][wrow] = wv1.w;
        *(float4*)&Xs[buf][xrow][xcol] = xv;
        __syncthreads();

        if (k0 + 16 < C) {
            wv0 = *(const float4*)(Wp + k0 + 16);
            wv1 = *(const float4*)(Wp + k0 + 20);
            xv  = *(const float4*)(Xp + (size_t)(k0 + 16) * HW);
            if (Ap) {
                const float a = Ap[k0 + 16], bb = Bp[k0 + 16];
                xv.x = fmaf(xv.x, a, bb); xv.y = fmaf(xv.y, a, bb);
                xv.z = fmaf(xv.z, a, bb); xv.w = fmaf(xv.w, a, bb);
            }
        }

        #pragma unroll
        for (int kk = 0; kk < 16; kk++) {
            const float4 av0 = *(const float4*)&Ws[buf][kk][ty8];
            const float4 av1 = *(const float4*)&Ws[buf][kk][ty8 + 4];
            const ulonglong2 bv = *(const ulonglong2*)&Xs[buf][kk][tx4];
            const ull a0 = pack2(av0.x, av0.x);
            const ull a1 = pack2(av0.y, av0.y);
            const ull a2 = pack2(av0.z, av0.z);
            const ull a3 = pack2(av0.w, av0.w);
            const ull a4 = pack2(av1.x, av1.x);
            const ull a5 = pack2(av1.y, av1.y);
            const ull a6 = pack2(av1.z, av1.z);
            const ull a7 = pack2(av1.w, av1.w);
            acc2[0][0] = ffma2(a0, bv.x, acc2[0][0]);
            acc2[0][1] = ffma2(a0, bv.y, acc2[0][1]);
            acc2[1][0] = ffma2(a1, bv.x, acc2[1][0]);
            acc2[1][1] = ffma2(a1, bv.y, acc2[1][1]);
            acc2[2][0] = ffma2(a2, bv.x, acc2[2][0]);
            acc2[2][1] = ffma2(a2, bv.y, acc2[2][1]);
            acc2[3][0] = ffma2(a3, bv.x, acc2[3][0]);
            acc2[3][1] = ffma2(a3, bv.y, acc2[3][1]);
            acc2[4][0] = ffma2(a4, bv.x, acc2[4][0]);
            acc2[4][1] = ffma2(a4, bv.y, acc2[4][1]);
            acc2[5][0] = ffma2(a5, bv.x, acc2[5][0]);
            acc2[5][1] = ffma2(a5, bv.y, acc2[5][1]);
            acc2[6][0] = ffma2(a6, bv.x, acc2[6][0]);
            acc2[6][1] = ffma2(a6, bv.y, acc2[6][1]);
            acc2[7][0] = ffma2(a7, bv.x, acc2[7][0]);
            acc2[7][1] = ffma2(a7, bv.y, acc2[7][1]);
        }
        buf ^= 1;
    }

    #pragma unroll
    for (int i = 0; i < 8; i++) {
        const int o = o0 + ty8 + i;
        const float bv = bias[o];
        const size_t oidx = ((size_t)n * M + o) * HW + t0 + tx4;
        float4 r;
        unpack2(acc2[i][0], r.x, r.y);
        unpack2(acc2[i][1], r.z, r.w);
        r.x += bv; r.y += bv; r.z += bv; r.w += bv;
        if (resid != nullptr) {
            float4 rv = *(const float4*)(resid + oidx);
            r.x += rv.x; r.y += rv.y; r.z += rv.z; r.w += rv.w;
        }
        *(float4*)(Out + oidx) = r;
    }
}

// ---------------------------------------------------------------------------
// Kernel 3: fused attention v4.
// Grid: NB*NH*2 = 512 CTAs, 256 threads, __launch_bounds__(256,3) so 3 CTAs
// fit per SM (regs<=85, smem 3x64KB=192KB <= 227KB) -> near-single wave.
// Each CTA: one (n,h), half the queries, 2 queries per lane.
// K,V pair-interleaved in smem; broadcast LDS.128; static softmax, raw ex2.
// ---------------------------------------------------------------------------
__global__ void __launch_bounds__(256, 3)
attn_kernel(const float* __restrict__ qkv, float* __restrict__ y)
{
    extern __shared__ ull sm2[];
    ull* k2s = sm2;            // [4][1024]
    ull* v2s = sm2 + 4 * HW;   // [4][1024]

    const int b  = blockIdx.x;        // (n*32 + h)*2 + qh
    const int qh = b & 1;
    const int h  = (b >> 1) & 31;
    const int n  = b >> 6;
    const int tid = threadIdx.x;      // 0..255

    const float* qbase = qkv + ((size_t)n * 3 * C + h * HD) * HW;
    const float* kbase = qkv + ((size_t)n * 3 * C + C + h * HD) * HW;
    const float* vbase = qkv + ((size_t)n * 3 * C + 2 * C + h * HD) * HW;

    for (int idx = tid; idx < 4 * HW; idx += 256) {
        const int j = idx >> 10;
        const int t = idx & 1023;
        k2s[idx] = pack2(kbase[(2 * j) * HW + t], kbase[(2 * j + 1) * HW + t]);
        v2s[idx] = pack2(vbase[(2 * j) * HW + t], vbase[(2 * j + 1) * HW + t]);
    }
    __syncthreads();

    // 1/sqrt(8) * log2(e)
    const float qscale = 0.35355339059327373f * 1.4426950408889634f;

    const int sA = qh * 512 + tid;          // query A
    const int sB = qh * 512 + 256 + tid;    // query B

    ull qA[4], qB[4];
    #pragma unroll
    for (int j = 0; j < 4; j++) {
        qA[j] = pack2(qbase[(2 * j) * HW + sA] * qscale,
                      qbase[(2 * j + 1) * HW + sA] * qscale);
        qB[j] = pack2(qbase[(2 * j) * HW + sB] * qscale,
                      qbase[(2 * j + 1) * HW + sB] * qscale);
    }

    ull lA = 0ull, lB = 0ull;
    ull accA[4], accB[4];
    #pragma unroll
    for (int j = 0; j < 4; j++) { accA[j] = 0ull; accB[j] = 0ull; }

    #pragma unroll 2
    for (int t0 = 0; t0 < HW; t0 += 2) {
        ulonglong2 kk0 = *(const ulonglong2*)(k2s + (0 << 10) + t0);
        ulonglong2 kk1 = *(const ulonglong2*)(k2s + (1 << 10) + t0);
        ulonglong2 kk2 = *(const ulonglong2*)(k2s + (2 << 10) + t0);
        ulonglong2 kk3 = *(const ulonglong2*)(k2s + (3 << 10) + t0);

        ull aA0 = 0ull, aA1 = 0ull, aB0 = 0ull, aB1 = 0ull;
        aA0 = ffma2(qA[0], kk0.x, aA0);  aA1 = ffma2(qA[0], kk0.y, aA1);
        aB0 = ffma2(qB[0], kk0.x, aB0);  aB1 = ffma2(qB[0], kk0.y, aB1);
        aA0 = ffma2(qA[1], kk1.x, aA0);  aA1 = ffma2(qA[1], kk1.y, aA1);
        aB0 = ffma2(qB[1], kk1.x, aB0);  aB1 = ffma2(qB[1], kk1.y, aB1);
        aA0 = ffma2(qA[2], kk2.x, aA0);  aA1 = ffma2(qA[2], kk2.y, aA1);
        aB0 = ffma2(qB[2], kk2.x, aB0);  aB1 = ffma2(qB[2], kk2.y, aB1);
        aA0 = ffma2(qA[3], kk3.x, aA0);  aA1 = ffma2(qA[3], kk3.y, aA1);
        aB0 = ffma2(qB[3], kk3.x, aB0);  aB1 = ffma2(qB[3], kk3.y, aB1);

        float xA0, xA1, zA0, zA1, xB0, xB1, zB0, zB1;
        unpack2(aA0, xA0, xA1);
        unpack2(aA1, zA0, zA1);
        unpack2(aB0, xB0, xB1);
        unpack2(aB1, zB0, zB1);
        const float pA0 = ex2f(xA0 + xA1);
        const float pA1 = ex2f(zA0 + zA1);
        const float pB0 = ex2f(xB0 + xB1);
        const float pB1 = ex2f(zB0 + zB1);
        lA = fadd2(lA, pack2(pA0, pA1));
        lB = fadd2(lB, pack2(pB0, pB1));
        const ull pA02 = pack2(pA0, pA0);
        const ull pA12 = pack2(pA1, pA1);
        const ull pB02 = pack2(pB0, pB0);
        const ull pB12 = pack2(pB1, pB1);

        ulonglong2 vv0 = *(const ulonglong2*)(v2s + (0 << 10) + t0);
        ulonglong2 vv1 = *(const ulonglong2*)(v2s + (1 << 10) + t0);
        ulonglong2 vv2 = *(const ulonglong2*)(v2s + (2 << 10) + t0);
        ulonglong2 vv3 = *(const ulonglong2*)(v2s + (3 << 10) + t0);

        accA[0] = ffma2(pA02, vv0.x, accA[0]);
        accA[0] = ffma2(pA12, vv0.y, accA[0]);
        accB[0] = ffma2(pB02, vv0.x, accB[0]);
        accB[0] = ffma2(pB12, vv0.y, accB[0]);
        accA[1] = ffma2(pA02, vv1.x, accA[1]);
        accA[1] = ffma2(pA12, vv1.y, accA[1]);
        accB[1] = ffma2(pB02, vv1.x, accB[1]);
        accB[1] = ffma2(pB12, vv1.y, accB[1]);
        accA[2] = ffma2(pA02, vv2.x, accA[2]);
        accA[2] = ffma2(pA12, vv2.y, accA[2]);
        accB[2] = ffma2(pB02, vv2.x, accB[2]);
        accB[2] = ffma2(pB12, vv2.y, accB[2]);
        accA[3] = ffma2(pA02, vv3.x, accA[3]);
        accA[3] = ffma2(pA12, vv3.y, accA[3]);
        accB[3] = ffma2(pB02, vv3.x, accB[3]);
        accB[3] = ffma2(pB12, vv3.y, accB[3]);
    }

    float la, lb;
    unpack2(lA, la, lb);
    const float invA = __fdividef(1.0f, la + lb);
    unpack2(lB, la, lb);
    const float invB = __fdividef(1.0f, la + lb);

    float* ybA = y + ((size_t)n * C + h * HD) * HW + sA;
    float* ybB = y + ((size_t)n * C + h * HD) * HW + sB;
    #pragma unroll
    for (int j = 0; j < 4; j++) {
        float lo, hi;
        unpack2(accA[j], lo, hi);
        ybA[(2 * j) * HW]     = lo * invA;
        ybA[(2 * j + 1) * HW] = hi * invA;
        unpack2(accB[j], lo, hi);
        ybB[(2 * j) * HW]     = lo * invB;
        ybB[(2 * j + 1) * HW] = hi * invB;
    }
}

// ---------------------------------------------------------------------------
extern "C" void kernel_launch(void* const* d_in, const int* in_sizes, int n_in,
                              void* d_out, int out_size)
{
    const float* x     = (const float*)d_in[0];
    const float* gn_w  = (const float*)d_in[1];
    const float* gn_b  = (const float*)d_in[2];
    const float* qkv_w = (const float*)d_in[3];
    const float* qkv_b = (const float*)d_in[4];
    const float* out_w = (const float*)d_in[5];
    const float* out_b = (const float*)d_in[6];
    float* out = (float*)d_out;

    float *qkv, *y, *A, *B;
    cudaGetSymbolAddress((void**)&qkv, g_qkv);
    cudaGetSymbolAddress((void**)&y,   g_y);
    cudaGetSymbolAddress((void**)&A,   g_A);
    cudaGetSymbolAddress((void**)&B,   g_B);

    // 1. GroupNorm stats -> per-(n,c) affine
    gn_stats_kernel<<<NB * NG, 256>>>(x, gn_w, gn_b, A, B);

    // 2. QKV projection with fused GN affine on X load
    {
        dim3 grid(NB, (3 * C) / 128, HW / 64);
        gemm_kernel<<<grid, 256>>>(qkv_w, x, qkv_b, nullptr, A, B, qkv, 3 * C);
    }

    // 3. Attention: 512 CTAs (2 per (n,h)), 256 threads, 64 KB dynamic smem
    {
        const int smem = 8 * HW * sizeof(ull);   // 65536
        cudaFuncSetAttribute(attn_kernel, cudaFuncAttributeMaxDynamicSharedMemorySize, smem);
        attn_kernel<<<NB * NH * 2, 256, smem>>>(qkv, y);
    }

    // 4. Output projection + bias + residual
    {
        dim3 grid(NB, C / 128, HW / 64);
        gemm_kernel<<<grid, 256>>>(out_w, y, out_b, x, nullptr, nullptr, out, C);
    }
}

// round 6
// speedup vs baseline: 1.0224x; 1.0224x over previous
#include <cuda_runtime.h>
#include <cuda_bf16.h>
#include <math.h>

// Problem constants
#define NB 8        // batch
#define C 256       // channels
#define HW 1024     // 32*32
#define NH 32       // heads
#define HD 8        // head dim
#define NG 8        // groupnorm groups
#define CG 32       // channels per group
#define GN_EPS 1e-5f

// Scratch (allocation-free rule: __device__ globals)
__device__ float g_qkv[(size_t)NB * 3 * C * HW];   // 24 MB
__device__ float g_y[(size_t)NB * C * HW];         // 8 MB
__device__ float g_A[NB * C];                      // per-(n,c) GN scale
__device__ float g_B[NB * C];                      // per-(n,c) GN shift

typedef unsigned long long ull;

// ---------------------------------------------------------------------------
// Packed f32x2 helpers (sm_103a FFMA2 path)
// ---------------------------------------------------------------------------
__device__ __forceinline__ ull pack2(float lo, float hi) {
    ull r;
    asm("mov.b64 %0, {%1, %2};" : "=l"(r) : "f"(lo), "f"(hi));
    return r;
}
__device__ __forceinline__ void unpack2(ull p, float& lo, float& hi) {
    asm("mov.b64 {%0, %1}, %2;" : "=f"(lo), "=f"(hi) : "l"(p));
}
__device__ __forceinline__ ull ffma2(ull a, ull b, ull c) {
    ull d;
    asm("fma.rn.f32x2 %0, %1, %2, %3;" : "=l"(d) : "l"(a), "l"(b), "l"(c));
    return d;
}
__device__ __forceinline__ ull fadd2(ull a, ull b) {
    ull d;
    asm("add.rn.f32x2 %0, %1, %2;" : "=l"(d) : "l"(a), "l"(b));
    return d;
}
__device__ __forceinline__ float ex2f(float x) {
    float y;
    asm("ex2.approx.f32 %0, %1;" : "=f"(y) : "f"(x));
    return y;
}

// ---------------------------------------------------------------------------
// Kernel 1: GroupNorm stats only.  One CTA per (n, group).
// Emits per-channel affine:  A[n,c] = gn_w[c]*rstd,  B[n,c] = gn_b[c]-mu*A.
// ---------------------------------------------------------------------------
__global__ void gn_stats_kernel(const float* __restrict__ x,
                                const float* __restrict__ w,
                                const float* __restrict__ b,
                                float* __restrict__ A,
                                float* __restrict__ B)
{
    const int n = blockIdx.x >> 3;
    const int g = blockIdx.x & 7;
    const size_t base = ((size_t)n * NG + g) * (CG * HW);
    const float4* xp = (const float4*)(x + base);

    float s = 0.f, ss = 0.f;
    for (int i = threadIdx.x; i < (CG * HW) / 4; i += 256) {
        float4 v = xp[i];
        s  += v.x + v.y + v.z + v.w;
        ss += v.x * v.x + v.y * v.y + v.z * v.z + v.w * v.w;
    }
    for (int o = 16; o > 0; o >>= 1) {
        s  += __shfl_xor_sync(0xffffffffu, s, o);
        ss += __shfl_xor_sync(0xffffffffu, ss, o);
    }
    __shared__ float rs[8], rss[8];
    __shared__ float s_mu, s_rstd;
    const int warp = threadIdx.x >> 5, lane = threadIdx.x & 31;
    if (lane == 0) { rs[warp] = s; rss[warp] = ss; }
    __syncthreads();
    if (threadIdx.x == 0) {
        float ts = 0.f, tss = 0.f;
        #pragma unroll
        for (int i = 0; i < 8; i++) { ts += rs[i]; tss += rss[i]; }
        const float inv_n = 1.0f / (CG * HW);
        float mu = ts * inv_n;
        float var = tss * inv_n - mu * mu;
        s_mu = mu;
        s_rstd = rsqrtf(var + GN_EPS);
    }
    __syncthreads();
    if (threadIdx.x < CG) {
        const int c = (g << 5) + threadIdx.x;
        const float a = w[c] * s_rstd;
        A[n * C + c] = a;
        B[n * C + c] = fmaf(-s_mu, a, b[c]);
    }
}

// ---------------------------------------------------------------------------
// Kernel 2/4: batched GEMM  Out[n][o][t] = sum_c W[o][c] * Xn[c][t] + bias[o]
// FUSE_GN: Xn = sA[c]*X[c][t] + sB[c] with the affine cached in smem.
// tile 128(o) x 64(t) x 16(k), 256 threads, 8x4 outputs per thread, f32x2.
// ---------------------------------------------------------------------------
template <bool FUSE_GN, bool RESID>
__global__ void __launch_bounds__(256, 3)
gemm_kernel(const float* __restrict__ W,
            const float* __restrict__ X,
            const float* __restrict__ bias,
            const float* __restrict__ resid,
            const float* __restrict__ Ac,
            const float* __restrict__ Bc,
            float* __restrict__ Out,
            int M)
{
    const int n  = blockIdx.x;
    const int o0 = blockIdx.y * 128;
    const int t0 = blockIdx.z * 64;

    __shared__ float Ws[2][16][132];
    __shared__ float Xs[2][16][64];
    __shared__ float sA[FUSE_GN ? C : 1];
    __shared__ float sB[FUSE_GN ? C : 1];

    const int tid = threadIdx.x;
    const int tx = tid & 15, ty = tid >> 4;
    const int ty8 = ty * 8, tx4 = tx * 4;

    if (FUSE_GN) {
        if (tid < C) {
            sA[tid] = Ac[n * C + tid];
            sB[tid] = Bc[n * C + tid];
        }
        __syncthreads();
    }

    ull acc2[8][2];
    #pragma unroll
    for (int i = 0; i < 8; i++) { acc2[i][0] = 0ull; acc2[i][1] = 0ull; }

    const int wrow = tid >> 1;
    const int wcol = (tid & 1) << 3;
    const int xrow = tid >> 4, xcol = (tid & 15) << 2;

    const float* Wp = W + (size_t)(o0 + wrow) * C + wcol;
    const float* Xp = X + ((size_t)n * C + xrow) * HW + t0 + xcol;

    float4 wv0 = *(const float4*)Wp;
    float4 wv1 = *(const float4*)(Wp + 4);
    float4 xv  = *(const float4*)Xp;
    if (FUSE_GN) {
        const float a = sA[xrow], bb = sB[xrow];
        xv.x = fmaf(xv.x, a, bb); xv.y = fmaf(xv.y, a, bb);
        xv.z = fmaf(xv.z, a, bb); xv.w = fmaf(xv.w, a, bb);
    }

    int buf = 0;
    for (int k0 = 0; k0 < C; k0 += 16) {
        Ws[buf][wcol + 0][wrow] = wv0.x;
        Ws[buf][wcol + 1][wrow] = wv0.y;
        Ws[buf][wcol + 2][wrow] = wv0.z;
        Ws[buf][wcol + 3][wrow] = wv0.w;
        Ws[buf][wcol + 4][wrow] = wv1.x;
        Ws[buf][wcol + 5][wrow] = wv1.y;
        Ws[buf][wcol + 6][wrow] = wv1.z;
        Ws[buf][wcol + 7][wrow] = wv1.w;
        *(float4*)&Xs[buf][xrow][xcol] = xv;
        __syncthreads();

        if (k0 + 16 < C) {
            wv0 = *(const float4*)(Wp + k0 + 16);
            wv1 = *(const float4*)(Wp + k0 + 20);
            xv  = *(const float4*)(Xp + (size_t)(k0 + 16) * HW);
            if (FUSE_GN) {
                const float a = sA[k0 + 16 + xrow], bb = sB[k0 + 16 + xrow];
                xv.x = fmaf(xv.x, a, bb); xv.y = fmaf(xv.y, a, bb);
                xv.z = fmaf(xv.z, a, bb); xv.w = fmaf(xv.w, a, bb);
            }
        }

        #pragma unroll
        for (int kk = 0; kk < 16; kk++) {
            const float4 av0 = *(const float4*)&Ws[buf][kk][ty8];
            const float4 av1 = *(const float4*)&Ws[buf][kk][ty8 + 4];
            const ulonglong2 bv = *(const ulonglong2*)&Xs[buf][kk][tx4];
            const ull a0 = pack2(av0.x, av0.x);
            const ull a1 = pack2(av0.y, av0.y);
            const ull a2 = pack2(av0.z, av0.z);
            const ull a3 = pack2(av0.w, av0.w);
            const ull a4 = pack2(av1.x, av1.x);
            const ull a5 = pack2(av1.y, av1.y);
            const ull a6 = pack2(av1.z, av1.z);
            const ull a7 = pack2(av1.w, av1.w);
            acc2[0][0] = ffma2(a0, bv.x, acc2[0][0]);
            acc2[0][1] = ffma2(a0, bv.y, acc2[0][1]);
            acc2[1][0] = ffma2(a1, bv.x, acc2[1][0]);
            acc2[1][1] = ffma2(a1, bv.y, acc2[1][1]);
            acc2[2][0] = ffma2(a2, bv.x, acc2[2][0]);
            acc2[2][1] = ffma2(a2, bv.y, acc2[2][1]);
            acc2[3][0] = ffma2(a3, bv.x, acc2[3][0]);
            acc2[3][1] = ffma2(a3, bv.y, acc2[3][1]);
            acc2[4][0] = ffma2(a4, bv.x, acc2[4][0]);
            acc2[4][1] = ffma2(a4, bv.y, acc2[4][1]);
            acc2[5][0] = ffma2(a5, bv.x, acc2[5][0]);
            acc2[5][1] = ffma2(a5, bv.y, acc2[5][1]);
            acc2[6][0] = ffma2(a6, bv.x, acc2[6][0]);
            acc2[6][1] = ffma2(a6, bv.y, acc2[6][1]);
            acc2[7][0] = ffma2(a7, bv.x, acc2[7][0]);
            acc2[7][1] = ffma2(a7, bv.y, acc2[7][1]);
        }
        buf ^= 1;
    }

    #pragma unroll
    for (int i = 0; i < 8; i++) {
        const int o = o0 + ty8 + i;
        const float bv = bias[o];
        const size_t oidx = ((size_t)n * M + o) * HW + t0 + tx4;
        float4 r;
        unpack2(acc2[i][0], r.x, r.y);
        unpack2(acc2[i][1], r.z, r.w);
        r.x += bv; r.y += bv; r.z += bv; r.w += bv;
        if (RESID) {
            float4 rv = *(const float4*)(resid + oidx);
            r.x += rv.x; r.y += rv.y; r.z += rv.z; r.w += rv.w;
        }
        *(float4*)(Out + oidx) = r;
    }
}

// ---------------------------------------------------------------------------
// Kernel 3: fused attention v5.
// Grid: NB*NH*2 = 512 CTAs, 256 threads, 3 CTAs/SM (smem 3x64KB=192 <= 227).
// Each CTA: one (n,h), half the queries, 2 queries per lane.
// K,V pair-interleaved in smem; broadcast LDS.128; static softmax, raw ex2.
// No inner unroll (keeps live ranges small -> no spills under the 85-reg cap).
// ---------------------------------------------------------------------------
__global__ void __launch_bounds__(256, 3)
attn_kernel(const float* __restrict__ qkv, float* __restrict__ y)
{
    extern __shared__ ull sm2[];
    ull* k2s = sm2;            // [4][1024]
    ull* v2s = sm2 + 4 * HW;   // [4][1024]

    const int b  = blockIdx.x;        // (n*32 + h)*2 + qh
    const int qh = b & 1;
    const int h  = (b >> 1) & 31;
    const int n  = b >> 6;
    const int tid = threadIdx.x;      // 0..255

    const float* qbase = qkv + ((size_t)n * 3 * C + h * HD) * HW;
    const float* kbase = qkv + ((size_t)n * 3 * C + C + h * HD) * HW;
    const float* vbase = qkv + ((size_t)n * 3 * C + 2 * C + h * HD) * HW;

    for (int idx = tid; idx < 4 * HW; idx += 256) {
        const int j = idx >> 10;
        const int t = idx & 1023;
        k2s[idx] = pack2(kbase[(2 * j) * HW + t], kbase[(2 * j + 1) * HW + t]);
        v2s[idx] = pack2(vbase[(2 * j) * HW + t], vbase[(2 * j + 1) * HW + t]);
    }
    __syncthreads();

    // 1/sqrt(8) * log2(e)
    const float qscale = 0.35355339059327373f * 1.4426950408889634f;

    const int sA = qh * 512 + tid;          // query A
    const int sB = qh * 512 + 256 + tid;    // query B

    ull qA[4], qB[4];
    #pragma unroll
    for (int j = 0; j < 4; j++) {
        qA[j] = pack2(qbase[(2 * j) * HW + sA] * qscale,
                      qbase[(2 * j + 1) * HW + sA] * qscale);
        qB[j] = pack2(qbase[(2 * j) * HW + sB] * qscale,
                      qbase[(2 * j + 1) * HW + sB] * qscale);
    }

    ull lA = 0ull, lB = 0ull;
    ull accA[4], accB[4];
    #pragma unroll
    for (int j = 0; j < 4; j++) { accA[j] = 0ull; accB[j] = 0ull; }

    #pragma unroll 1
    for (int t0 = 0; t0 < HW; t0 += 2) {
        const ulonglong2 kk0 = *(const ulonglong2*)(k2s + 0 * HW + t0);
        const ulonglong2 kk1 = *(const ulonglong2*)(k2s + 1 * HW + t0);
        const ulonglong2 kk2 = *(const ulonglong2*)(k2s + 2 * HW + t0);
        const ulonglong2 kk3 = *(const ulonglong2*)(k2s + 3 * HW + t0);

        ull aA0 = 0ull, aA1 = 0ull, aB0 = 0ull, aB1 = 0ull;
        aA0 = ffma2(qA[0], kk0.x, aA0);  aA1 = ffma2(qA[0], kk0.y, aA1);
        aB0 = ffma2(qB[0], kk0.x, aB0);  aB1 = ffma2(qB[0], kk0.y, aB1);
        aA0 = ffma2(qA[1], kk1.x, aA0);  aA1 = ffma2(qA[1], kk1.y, aA1);
        aB0 = ffma2(qB[1], kk1.x, aB0);  aB1 = ffma2(qB[1], kk1.y, aB1);
        aA0 = ffma2(qA[2], kk2.x, aA0);  aA1 = ffma2(qA[2], kk2.y, aA1);
        aB0 = ffma2(qB[2], kk2.x, aB0);  aB1 = ffma2(qB[2], kk2.y, aB1);
        aA0 = ffma2(qA[3], kk3.x, aA0);  aA1 = ffma2(qA[3], kk3.y, aA1);
        aB0 = ffma2(qB[3], kk3.x, aB0);  aB1 = ffma2(qB[3], kk3.y, aB1);

        float xA0, xA1, zA0, zA1, xB0, xB1, zB0, zB1;
        unpack2(aA0, xA0, xA1);
        unpack2(aA1, zA0, zA1);
        unpack2(aB0, xB0, xB1);
        unpack2(aB1, zB0, zB1);
        const float pA0 = ex2f(xA0 + xA1);
        const float pA1 = ex2f(zA0 + zA1);
        const float pB0 = ex2f(xB0 + xB1);
        const float pB1 = ex2f(zB0 + zB1);
        lA = fadd2(lA, pack2(pA0, pA1));
        lB = fadd2(lB, pack2(pB0, pB1));
        const ull pA02 = pack2(pA0, pA0);
        const ull pA12 = pack2(pA1, pA1);
        const ull pB02 = pack2(pB0, pB0);
        const ull pB12 = pack2(pB1, pB1);

        const ulonglong2 vv0 = *(const ulonglong2*)(v2s + 0 * HW + t0);
        const ulonglong2 vv1 = *(const ulonglong2*)(v2s + 1 * HW + t0);
        const ulonglong2 vv2 = *(const ulonglong2*)(v2s + 2 * HW + t0);
        const ulonglong2 vv3 = *(const ulonglong2*)(v2s + 3 * HW + t0);

        accA[0] = ffma2(pA02, vv0.x, accA[0]);
        accA[0] = ffma2(pA12, vv0.y, accA[0]);
        accB[0] = ffma2(pB02, vv0.x, accB[0]);
        accB[0] = ffma2(pB12, vv0.y, accB[0]);
        accA[1] = ffma2(pA02, vv1.x, accA[1]);
        accA[1] = ffma2(pA12, vv1.y, accA[1]);
        accB[1] = ffma2(pB02, vv1.x, accB[1]);
        accB[1] = ffma2(pB12, vv1.y, accB[1]);
        accA[2] = ffma2(pA02, vv2.x, accA[2]);
        accA[2] = ffma2(pA12, vv2.y, accA[2]);
        accB[2] = ffma2(pB02, vv2.x, accB[2]);
        accB[2] = ffma2(pB12, vv2.y, accB[2]);
        accA[3] = ffma2(pA02, vv3.x, accA[3]);
        accA[3] = ffma2(pA12, vv3.y, accA[3]);
        accB[3] = ffma2(pB02, vv3.x, accB[3]);
        accB[3] = ffma2(pB12, vv3.y, accB[3]);
    }

    float la, lb;
    unpack2(lA, la, lb);
    const float invA = __fdividef(1.0f, la + lb);
    unpack2(lB, la, lb);
    const float invB = __fdividef(1.0f, la + lb);

    float* ybA = y + ((size_t)n * C + h * HD) * HW + sA;
    float* ybB = y + ((size_t)n * C + h * HD) * HW + sB;
    #pragma unroll
    for (int j = 0; j < 4; j++) {
        float lo, hi;
        unpack2(accA[j], lo, hi);
        ybA[(2 * j) * HW]     = lo * invA;
        ybA[(2 * j + 1) * HW] = hi * invA;
        unpack2(accB[j], lo, hi);
        ybB[(2 * j) * HW]     = lo * invB;
        ybB[(2 * j + 1) * HW] = hi * invB;
    }
}

// ---------------------------------------------------------------------------
extern "C" void kernel_launch(void* const* d_in, const int* in_sizes, int n_in,
                              void* d_out, int out_size)
{
    const float* x     = (const float*)d_in[0];
    const float* gn_w  = (const float*)d_in[1];
    const float* gn_b  = (const float*)d_in[2];
    const float* qkv_w = (const float*)d_in[3];
    const float* qkv_b = (const float*)d_in[4];
    const float* out_w = (const float*)d_in[5];
    const float* out_b = (const float*)d_in[6];
    float* out = (float*)d_out;

    float *qkv, *y, *A, *B;
    cudaGetSymbolAddress((void**)&qkv, g_qkv);
    cudaGetSymbolAddress((void**)&y,   g_y);
    cudaGetSymbolAddress((void**)&A,   g_A);
    cudaGetSymbolAddress((void**)&B,   g_B);

    // 1. GroupNorm stats -> per-(n,c) affine
    gn_stats_kernel<<<NB * NG, 256>>>(x, gn_w, gn_b, A, B);

    // 2. QKV projection with fused GN affine on X load
    {
        dim3 grid(NB, (3 * C) / 128, HW / 64);
        gemm_kernel<true, false><<<grid, 256>>>(qkv_w, x, qkv_b, nullptr, A, B, qkv, 3 * C);
    }

    // 3. Attention: 512 CTAs (2 per (n,h)), 256 threads, 64 KB dynamic smem
    {
        const int smem = 8 * HW * sizeof(ull);   // 65536
        cudaFuncSetAttribute(attn_kernel, cudaFuncAttributeMaxDynamicSharedMemorySize, smem);
        attn_kernel<<<NB * NH * 2, 256, smem>>>(qkv, y);
    }

    // 4. Output projection + bias + residual
    {
        dim3 grid(NB, C / 128, HW / 64);
        gemm_kernel<false, true><<<grid, 256>>>(out_w, y, out_b, x, nullptr, nullptr, out, C);
    }
}

// round 7
// speedup vs baseline: 1.9543x; 1.9116x over previous
#include <cuda_runtime.h>
#include <cuda_bf16.h>
#include <cuda_fp16.h>
#include <math.h>

// Problem constants
#define NB 8        // batch
#define C 256       // channels
#define HW 1024     // 32*32
#define NH 32       // heads
#define HD 8        // head dim
#define NG 8        // groupnorm groups
#define CG 32       // channels per group
#define GN_EPS 1e-5f

// Scratch (allocation-free rule: __device__ globals)
__device__ float g_qkv[(size_t)NB * 3 * C * HW];   // 24 MB
__device__ float g_y[(size_t)NB * C * HW];         // 8 MB
__device__ float g_A[NB * C];                      // per-(n,c) GN scale
__device__ float g_B[NB * C];                      // per-(n,c) GN shift

typedef unsigned long long ull;
typedef unsigned int uint;

// ---------------------------------------------------------------------------
// Packed f32x2 helpers (sm_103a FFMA2 path)
// ---------------------------------------------------------------------------
__device__ __forceinline__ ull pack2(float lo, float hi) {
    ull r;
    asm("mov.b64 %0, {%1, %2};" : "=l"(r) : "f"(lo), "f"(hi));
    return r;
}
__device__ __forceinline__ void unpack2(ull p, float& lo, float& hi) {
    asm("mov.b64 {%0, %1}, %2;" : "=f"(lo), "=f"(hi) : "l"(p));
}
__device__ __forceinline__ ull ffma2(ull a, ull b, ull c) {
    ull d;
    asm("fma.rn.f32x2 %0, %1, %2, %3;" : "=l"(d) : "l"(a), "l"(b), "l"(c));
    return d;
}

// fp16 / mma helpers
__device__ __forceinline__ uint cvt_f16x2(float lo, float hi) {
    uint r;
    asm("cvt.rn.f16x2.f32 %0, %1, %2;" : "=r"(r) : "f"(hi), "f"(lo));
    return r;
}
__device__ __forceinline__ uint ex2_f16x2(uint x) {
    uint r;
    asm("ex2.approx.f16x2 %0, %1;" : "=r"(r) : "r"(x));
    return r;
}
__device__ __forceinline__ float sum_h2(uint p) {
    __half2 h = *reinterpret_cast<__half2*>(&p);
    float2 f = __half22float2(h);
    return f.x + f.y;
}
// D = A(16x16 f16) * B(16x8 f16) + C (f32)
__device__ __forceinline__ void mma16816(float& d0, float& d1, float& d2, float& d3,
                                         uint a0, uint a1, uint a2, uint a3,
                                         uint b0, uint b1,
                                         float c0, float c1, float c2, float c3) {
    asm("mma.sync.aligned.m16n8k16.row.col.f32.f16.f16.f32 "
        "{%0,%1,%2,%3}, {%4,%5,%6,%7}, {%8,%9}, {%10,%11,%12,%13};"
        : "=f"(d0), "=f"(d1), "=f"(d2), "=f"(d3)
        : "r"(a0), "r"(a1), "r"(a2), "r"(a3), "r"(b0), "r"(b1),
          "f"(c0), "f"(c1), "f"(c2), "f"(c3));
}

// ---------------------------------------------------------------------------
// Kernel 1: GroupNorm stats only.  One CTA per (n, group).
// ---------------------------------------------------------------------------
__global__ void gn_stats_kernel(const float* __restrict__ x,
                                const float* __restrict__ w,
                                const float* __restrict__ b,
                                float* __restrict__ A,
                                float* __restrict__ B)
{
    const int n = blockIdx.x >> 3;
    const int g = blockIdx.x & 7;
    const size_t base = ((size_t)n * NG + g) * (CG * HW);
    const float4* xp = (const float4*)(x + base);

    float s = 0.f, ss = 0.f;
    for (int i = threadIdx.x; i < (CG * HW) / 4; i += 256) {
        float4 v = xp[i];
        s  += v.x + v.y + v.z + v.w;
        ss += v.x * v.x + v.y * v.y + v.z * v.z + v.w * v.w;
    }
    for (int o = 16; o > 0; o >>= 1) {
        s  += __shfl_xor_sync(0xffffffffu, s, o);
        ss += __shfl_xor_sync(0xffffffffu, ss, o);
    }
    __shared__ float rs[8], rss[8];
    __shared__ float s_mu, s_rstd;
    const int warp = threadIdx.x >> 5, lane = threadIdx.x & 31;
    if (lane == 0) { rs[warp] = s; rss[warp] = ss; }
    __syncthreads();
    if (threadIdx.x == 0) {
        float ts = 0.f, tss = 0.f;
        #pragma unroll
        for (int i = 0; i < 8; i++) { ts += rs[i]; tss += rss[i]; }
        const float inv_n = 1.0f / (CG * HW);
        float mu = ts * inv_n;
        float var = tss * inv_n - mu * mu;
        s_mu = mu;
        s_rstd = rsqrtf(var + GN_EPS);
    }
    __syncthreads();
    if (threadIdx.x < CG) {
        const int c = (g << 5) + threadIdx.x;
        const float a = w[c] * s_rstd;
        A[n * C + c] = a;
        B[n * C + c] = fmaf(-s_mu, a, b[c]);
    }
}

// ---------------------------------------------------------------------------
// Kernel 2/4: batched GEMM (FFMA2, unchanged from R5 — known good)
// ---------------------------------------------------------------------------
template <bool FUSE_GN, bool RESID>
__global__ void __launch_bounds__(256, 3)
gemm_kernel(const float* __restrict__ W,
            const float* __restrict__ X,
            const float* __restrict__ bias,
            const float* __restrict__ resid,
            const float* __restrict__ Ac,
            const float* __restrict__ Bc,
            float* __restrict__ Out,
            int M)
{
    const int n  = blockIdx.x;
    const int o0 = blockIdx.y * 128;
    const int t0 = blockIdx.z * 64;

    __shared__ float Ws[2][16][132];
    __shared__ float Xs[2][16][64];
    __shared__ float sA[FUSE_GN ? C : 1];
    __shared__ float sB[FUSE_GN ? C : 1];

    const int tid = threadIdx.x;
    const int tx = tid & 15, ty = tid >> 4;
    const int ty8 = ty * 8, tx4 = tx * 4;

    if (FUSE_GN) {
        if (tid < C) {
            sA[tid] = Ac[blockIdx.x * C + tid];
            sB[tid] = Bc[blockIdx.x * C + tid];
        }
        __syncthreads();
    }

    ull acc2[8][2];
    #pragma unroll
    for (int i = 0; i < 8; i++) { acc2[i][0] = 0ull; acc2[i][1] = 0ull; }

    const int wrow = tid >> 1;
    const int wcol = (tid & 1) << 3;
    const int xrow = tid >> 4, xcol = (tid & 15) << 2;

    const float* Wp = W + (size_t)(o0 + wrow) * C + wcol;
    const float* Xp = X + ((size_t)n * C + xrow) * HW + t0 + xcol;

    float4 wv0 = *(const float4*)Wp;
    float4 wv1 = *(const float4*)(Wp + 4);
    float4 xv  = *(const float4*)Xp;
    if (FUSE_GN) {
        const float a = sA[xrow], bb = sB[xrow];
        xv.x = fmaf(xv.x, a, bb); xv.y = fmaf(xv.y, a, bb);
        xv.z = fmaf(xv.z, a, bb); xv.w = fmaf(xv.w, a, bb);
    }

    int buf = 0;
    for (int k0 = 0; k0 < C; k0 += 16) {
        Ws[buf][wcol + 0][wrow] = wv0.x;
        Ws[buf][wcol + 1][wrow] = wv0.y;
        Ws[buf][wcol + 2][wrow] = wv0.z;
        Ws[buf][wcol + 3][wrow] = wv0.w;
        Ws[buf][wcol + 4][wrow] = wv1.x;
        Ws[buf][wcol + 5][wrow] = wv1.y;
        Ws[buf][wcol + 6][wrow] = wv1.z;
        Ws[buf][wcol + 7][wrow] = wv1.w;
        *(float4*)&Xs[buf][xrow][xcol] = xv;
        __syncthreads();

        if (k0 + 16 < C) {
            wv0 = *(const float4*)(Wp + k0 + 16);
            wv1 = *(const float4*)(Wp + k0 + 20);
            xv  = *(const float4*)(Xp + (size_t)(k0 + 16) * HW);
            if (FUSE_GN) {
                const float a = sA[k0 + 16 + xrow], bb = sB[k0 + 16 + xrow];
                xv.x = fmaf(xv.x, a, bb); xv.y = fmaf(xv.y, a, bb);
                xv.z = fmaf(xv.z, a, bb); xv.w = fmaf(xv.w, a, bb);
            }
        }

        #pragma unroll
        for (int kk = 0; kk < 16; kk++) {
            const float4 av0 = *(const float4*)&Ws[buf][kk][ty8];
            const float4 av1 = *(const float4*)&Ws[buf][kk][ty8 + 4];
            const ulonglong2 bv = *(const ulonglong2*)&Xs[buf][kk][tx4];
            const ull a0 = pack2(av0.x, av0.x);
            const ull a1 = pack2(av0.y, av0.y);
            const ull a2 = pack2(av0.z, av0.z);
            const ull a3 = pack2(av0.w, av0.w);
            const ull a4 = pack2(av1.x, av1.x);
            const ull a5 = pack2(av1.y, av1.y);
            const ull a6 = pack2(av1.z, av1.z);
            const ull a7 = pack2(av1.w, av1.w);
            acc2[0][0] = ffma2(a0, bv.x, acc2[0][0]);
            acc2[0][1] = ffma2(a0, bv.y, acc2[0][1]);
            acc2[1][0] = ffma2(a1, bv.x, acc2[1][0]);
            acc2[1][1] = ffma2(a1, bv.y, acc2[1][1]);
            acc2[2][0] = ffma2(a2, bv.x, acc2[2][0]);
            acc2[2][1] = ffma2(a2, bv.y, acc2[2][1]);
            acc2[3][0] = ffma2(a3, bv.x, acc2[3][0]);
            acc2[3][1] = ffma2(a3, bv.y, acc2[3][1]);
            acc2[4][0] = ffma2(a4, bv.x, acc2[4][0]);
            acc2[4][1] = ffma2(a4, bv.y, acc2[4][1]);
            acc2[5][0] = ffma2(a5, bv.x, acc2[5][0]);
            acc2[5][1] = ffma2(a5, bv.y, acc2[5][1]);
            acc2[6][0] = ffma2(a6, bv.x, acc2[6][0]);
            acc2[6][1] = ffma2(a6, bv.y, acc2[6][1]);
            acc2[7][0] = ffma2(a7, bv.x, acc2[7][0]);
            acc2[7][1] = ffma2(a7, bv.y, acc2[7][1]);
        }
        buf ^= 1;
    }

    #pragma unroll
    for (int i = 0; i < 8; i++) {
        const int o = o0 + ty8 + i;
        const float bv = bias[o];
        const size_t oidx = ((size_t)n * M + o) * HW + t0 + tx4;
        float4 r;
        unpack2(acc2[i][0], r.x, r.y);
        unpack2(acc2[i][1], r.z, r.w);
        r.x += bv; r.y += bv; r.z += bv; r.w += bv;
        if (RESID) {
            float4 rv = *(const float4*)(resid + oidx);
            r.x += rv.x; r.y += rv.y; r.z += rv.z; r.w += rv.w;
        }
        *(float4*)(Out + oidx) = r;
    }
}

// ---------------------------------------------------------------------------
// Kernel 3: fused attention v6 — fp16 tensor cores (mma.sync m16n8k16).
// One CTA per (n,h), 256 threads (8 warps), each warp owns 8 q-strips of 16.
// QK: A=Q (k-dim = 8 head dims, upper 8 zero), B=K^T; static softmax via
// ex2.approx.f16x2 (scale*log2e folded into Q); P frags feed AV mma directly.
// K smem: half2 (d2j,d2j+1) [4][1024], XOR-swizzled. V smem: half2 key-pairs
// [8][512], XOR-swizzled. Both B-fragment gathers bank-conflict-free.
// ---------------------------------------------------------------------------
__global__ void __launch_bounds__(256, 2)
attn_kernel(const float* __restrict__ qkv, float* __restrict__ y)
{
    __shared__ uint Kh[4096];   // [j][key^(j<<3)]  j = d-pair
    __shared__ uint Vs[4096];   // [d][kp^(d<<2)]   kp = key-pair

    const int b = blockIdx.x;        // n*32 + h
    const int h = b & 31;
    const int n = b >> 5;
    const int tid = threadIdx.x;
    const int warp = tid >> 5, lane = tid & 31;
    const int g = lane >> 2, t = lane & 3;

    const float* qbase = qkv + ((size_t)n * 3 * C + h * HD) * HW;
    const float* kbase = qbase + (size_t)C * HW;
    const float* vbase = qbase + (size_t)2 * C * HW;

    // Fill K (pair-interleaved half2, swizzled)
    for (int idx = tid; idx < 4096; idx += 256) {
        const int j = idx >> 10, key = idx & 1023;
        __half2 hh = __floats2half2_rn(kbase[(2 * j) * HW + key],
                                       kbase[(2 * j + 1) * HW + key]);
        Kh[(j << 10) | (key ^ (j << 3))] = *(uint*)&hh;
    }
    // Fill V (key-pair half2 per d-row, swizzled)
    for (int idx = tid; idx < 4096; idx += 256) {
        const int d = idx >> 9, kp = idx & 511;
        const float2 v2 = *(const float2*)(vbase + (size_t)d * HW + 2 * kp);
        __half2 hh = __floats2half2_rn(v2.x, v2.y);
        Vs[(d << 9) | (kp ^ (d << 2))] = *(uint*)&hh;
    }
    __syncthreads();

    // 1/sqrt(8) * log2(e) folded into Q before fp16 rounding
    const float qscale = 0.35355339059327373f * 1.4426950408889634f;

    // Q fragments: 8 strips, rows q0+g / q0+8+g, cols (d) 2t, 2t+1
    uint qa0[8], qa1[8];
    #pragma unroll
    for (int s = 0; s < 8; s++) {
        const int q0 = (warp + 8 * s) << 4;
        const float* qd0 = qbase + (2 * t) * HW;
        const float* qd1 = qbase + (2 * t + 1) * HW;
        qa0[s] = cvt_f16x2(qd0[q0 + g] * qscale,     qd1[q0 + g] * qscale);
        qa1[s] = cvt_f16x2(qd0[q0 + 8 + g] * qscale, qd1[q0 + 8 + g] * qscale);
    }

    float pv[8][4];
    float l0[8], l1[8];
    #pragma unroll
    for (int s = 0; s < 8; s++) {
        pv[s][0] = pv[s][1] = pv[s][2] = pv[s][3] = 0.f;
        l0[s] = l1[s] = 0.f;
    }

    const uint zero = 0u;

    #pragma unroll 1
    for (int kb = 0; kb < 64; kb++) {
        const int key0 = kb << 4;
        // K fragments for the two key octets (B of QK mma)
        const uint kf0 = Kh[(t << 10) | ((key0 + g) ^ (t << 3))];
        const uint kf1 = Kh[(t << 10) | ((key0 + 8 + g) ^ (t << 3))];
        // V fragments (B of AV mma): keys 0-7 and 8-15 of this block
        const int kp0 = kb << 3;
        const uint vf0 = Vs[(g << 9) | ((kp0 + t) ^ (g << 2))];
        const uint vf1 = Vs[(g << 9) | ((kp0 + 4 + t) ^ (g << 2))];

        #pragma unroll
        for (int s = 0; s < 8; s++) {
            float c0, c1, c2, c3, d0, d1, d2, d3;
            // scores, keys 0-7 and 8-15 (k-dim = head dims, upper half zero)
            mma16816(c0, c1, c2, c3, qa0[s], qa1[s], zero, zero, kf0, zero,
                     0.f, 0.f, 0.f, 0.f);
            mma16816(d0, d1, d2, d3, qa0[s], qa1[s], zero, zero, kf1, zero,
                     0.f, 0.f, 0.f, 0.f);
            // P = 2^score  (f16x2 MUFU)
            const uint pa0 = ex2_f16x2(cvt_f16x2(c0, c1));
            const uint pa1 = ex2_f16x2(cvt_f16x2(c2, c3));
            const uint pa2 = ex2_f16x2(cvt_f16x2(d0, d1));
            const uint pa3 = ex2_f16x2(cvt_f16x2(d2, d3));
            // row-sum accumulation (f32)
            l0[s] += sum_h2(pa0) + sum_h2(pa2);
            l1[s] += sum_h2(pa1) + sum_h2(pa3);
            // PV += P * V
            mma16816(pv[s][0], pv[s][1], pv[s][2], pv[s][3],
                     pa0, pa1, pa2, pa3, vf0, vf1,
                     pv[s][0], pv[s][1], pv[s][2], pv[s][3]);
        }
    }

    // Epilogue: reduce row sums across the 4 lanes of each row, normalize, store
    float* yb = y + ((size_t)n * C + h * HD) * HW;
    #pragma unroll
    for (int s = 0; s < 8; s++) {
        float la = l0[s], lb = l1[s];
        la += __shfl_xor_sync(0xffffffffu, la, 1);
        la += __shfl_xor_sync(0xffffffffu, la, 2);
        lb += __shfl_xor_sync(0xffffffffu, lb, 1);
        lb += __shfl_xor_sync(0xffffffffu, lb, 2);
        const float inva = __fdividef(1.0f, la);
        const float invb = __fdividef(1.0f, lb);
        const int q0 = (warp + 8 * s) << 4;
        yb[(2 * t) * HW + q0 + g]         = pv[s][0] * inva;
        yb[(2 * t + 1) * HW + q0 + g]     = pv[s][1] * inva;
        yb[(2 * t) * HW + q0 + 8 + g]     = pv[s][2] * invb;
        yb[(2 * t + 1) * HW + q0 + 8 + g] = pv[s][3] * invb;
    }
}

// ---------------------------------------------------------------------------
extern "C" void kernel_launch(void* const* d_in, const int* in_sizes, int n_in,
                              void* d_out, int out_size)
{
    const float* x     = (const float*)d_in[0];
    const float* gn_w  = (const float*)d_in[1];
    const float* gn_b  = (const float*)d_in[2];
    const float* qkv_w = (const float*)d_in[3];
    const float* qkv_b = (const float*)d_in[4];
    const float* out_w = (const float*)d_in[5];
    const float* out_b = (const float*)d_in[6];
    float* out = (float*)d_out;

    float *qkv, *y, *A, *B;
    cudaGetSymbolAddress((void**)&qkv, g_qkv);
    cudaGetSymbolAddress((void**)&y,   g_y);
    cudaGetSymbolAddress((void**)&A,   g_A);
    cudaGetSymbolAddress((void**)&B,   g_B);

    // 1. GroupNorm stats -> per-(n,c) affine
    gn_stats_kernel<<<NB * NG, 256>>>(x, gn_w, gn_b, A, B);

    // 2. QKV projection with fused GN affine on X load
    {
        dim3 grid(NB, (3 * C) / 128, HW / 64);
        gemm_kernel<true, false><<<grid, 256>>>(qkv_w, x, qkv_b, nullptr, A, B, qkv, 3 * C);
    }

    // 3. Attention: 256 CTAs (1 per (n,h)), 256 threads, tensor-core path
    attn_kernel<<<NB * NH, 256>>>(qkv, y);

    // 4. Output projection + bias + residual
    {
        dim3 grid(NB, C / 128, HW / 64);
        gemm_kernel<false, true><<<grid, 256>>>(out_w, y, out_b, x, nullptr, nullptr, out, C);
    }
}

// round 8
// speedup vs baseline: 3.2846x; 1.6807x over previous
#include <cuda_runtime.h>
#include <cuda_bf16.h>
#include <cuda_fp16.h>
#include <math.h>

// Problem constants
#define NB 8        // batch
#define C 256       // channels
#define HW 1024     // 32*32
#define NH 32       // heads
#define HD 8        // head dim
#define NG 8        // groupnorm groups
#define CG 32       // channels per group
#define GN_EPS 1e-5f

// Scratch (allocation-free rule: __device__ globals)
__device__ float g_qkv[(size_t)NB * 3 * C * HW];   // 24 MB
__device__ float g_y[(size_t)NB * C * HW];         // 8 MB
__device__ float g_A[NB * C];                      // per-(n,c) GN scale
__device__ float g_B[NB * C];                      // per-(n,c) GN shift

typedef unsigned int uint;

// ---------------------------------------------------------------------------
// fp16 / mma helpers
// ---------------------------------------------------------------------------
__device__ __forceinline__ uint cvt_f16x2(float lo, float hi) {
    uint r;
    asm("cvt.rn.f16x2.f32 %0, %1, %2;" : "=r"(r) : "f"(hi), "f"(lo));
    return r;
}
__device__ __forceinline__ uint ex2_f16x2(uint x) {
    uint r;
    asm("ex2.approx.f16x2 %0, %1;" : "=r"(r) : "r"(x));
    return r;
}
__device__ __forceinline__ float sum_h2(uint p) {
    __half2 h = *reinterpret_cast<__half2*>(&p);
    float2 f = __half22float2(h);
    return f.x + f.y;
}
// D = A(16x16 f16) * B(16x8 f16) + C (f32)
__device__ __forceinline__ void mma16816(float& d0, float& d1, float& d2, float& d3,
                                         uint a0, uint a1, uint a2, uint a3,
                                         uint b0, uint b1,
                                         float c0, float c1, float c2, float c3) {
    asm("mma.sync.aligned.m16n8k16.row.col.f32.f16.f16.f32 "
        "{%0,%1,%2,%3}, {%4,%5,%6,%7}, {%8,%9}, {%10,%11,%12,%13};"
        : "=f"(d0), "=f"(d1), "=f"(d2), "=f"(d3)
        : "r"(a0), "r"(a1), "r"(a2), "r"(a3), "r"(b0), "r"(b1),
          "f"(c0), "f"(c1), "f"(c2), "f"(c3));
}

// ---------------------------------------------------------------------------
// Kernel 1: GroupNorm stats only.  One CTA per (n, group).
// ---------------------------------------------------------------------------
__global__ void gn_stats_kernel(const float* __restrict__ x,
                                const float* __restrict__ w,
                                const float* __restrict__ b,
                                float* __restrict__ A,
                                float* __restrict__ B)
{
    const int n = blockIdx.x >> 3;
    const int g = blockIdx.x & 7;
    const size_t base = ((size_t)n * NG + g) * (CG * HW);
    const float4* xp = (const float4*)(x + base);

    float s = 0.f, ss = 0.f;
    for (int i = threadIdx.x; i < (CG * HW) / 4; i += 256) {
        float4 v = xp[i];
        s  += v.x + v.y + v.z + v.w;
        ss += v.x * v.x + v.y * v.y + v.z * v.z + v.w * v.w;
    }
    for (int o = 16; o > 0; o >>= 1) {
        s  += __shfl_xor_sync(0xffffffffu, s, o);
        ss += __shfl_xor_sync(0xffffffffu, ss, o);
    }
    __shared__ float rs[8], rss[8];
    __shared__ float s_mu, s_rstd;
    const int warp = threadIdx.x >> 5, lane = threadIdx.x & 31;
    if (lane == 0) { rs[warp] = s; rss[warp] = ss; }
    __syncthreads();
    if (threadIdx.x == 0) {
        float ts = 0.f, tss = 0.f;
        #pragma unroll
        for (int i = 0; i < 8; i++) { ts += rs[i]; tss += rss[i]; }
        const float inv_n = 1.0f / (CG * HW);
        float mu = ts * inv_n;
        float var = tss * inv_n - mu * mu;
        s_mu = mu;
        s_rstd = rsqrtf(var + GN_EPS);
    }
    __syncthreads();
    if (threadIdx.x < CG) {
        const int c = (g << 5) + threadIdx.x;
        const float a = w[c] * s_rstd;
        A[n * C + c] = a;
        B[n * C + c] = fmaf(-s_mu, a, b[c]);
    }
}

// ---------------------------------------------------------------------------
// Kernel 2/4: batched GEMM v4 — fp16 tensor cores (mma.sync m16n8k16).
// Out[n][o][t] = sum_c W[o][c]*Xn[c][t] + bias[o]  (+residual)
// FUSE_GN: Xn = sA[c]*X[c][t]+sB[c], folded into the fp32->fp16 conversion.
// CTA tile 128(o) x 128(t) x 16(k), 256 thr = 8 warps (4M x 2N),
// warp tile 32x64 = 2x8 mma tiles, f32 accumulate, double-buffered smem.
// Smem layouts (validated fragment patterns from the attention kernel):
//   Wt[row][cp ^ ((row>>2&1)<<2)]  : half2 = (W[row][2cp], W[row][2cp+1])
//   Xt[cp][t ^ ((cp&3)<<3)]        : half2 = (X[2cp][t],  X[2cp+1][t])
// Both A and B fragment gathers are 32-bank conflict-free.
// ---------------------------------------------------------------------------
template <bool FUSE_GN, bool RESID>
__global__ void __launch_bounds__(256, 2)
gemm_h_kernel(const float* __restrict__ W,
              const float* __restrict__ X,
              const float* __restrict__ bias,
              const float* __restrict__ resid,
              const float* __restrict__ Ac,
              const float* __restrict__ Bc,
              float* __restrict__ Out,
              int M)
{
    const int n  = blockIdx.x;
    const int o0 = blockIdx.y * 128;
    const int t0 = blockIdx.z * 128;

    __shared__ uint Wt[2][128][8];
    __shared__ uint Xt[2][8][128];
    __shared__ float sA[FUSE_GN ? C : 1];
    __shared__ float sB[FUSE_GN ? C : 1];

    const int tid  = threadIdx.x;
    const int warp = tid >> 5, lane = tid & 31;
    const int g  = lane >> 2, tq = lane & 3;
    const int wm = (warp & 3) << 5;        // warp m offset (0..96)
    const int wn = (warp >> 2) << 6;       // warp n offset (0 or 64)

    if (FUSE_GN) {
        if (tid < C) {
            sA[tid] = Ac[n * C + tid];
            sB[tid] = Bc[n * C + tid];
        }
        __syncthreads();
    }

    // Loader indices
    const int row_w = tid >> 1;                 // 0..127 (o-row)
    const int cb    = (tid & 1) << 3;           // 0 or 8 (k offset)
    const int cp_x  = tid >> 5;                 // 0..7 (c-pair)
    const int tb    = lane << 2;                // 0..124 (t chunk)

    const float* Wp  = W + (size_t)(o0 + row_w) * C + cb;
    const float* Xp0 = X + ((size_t)n * C + 2 * cp_x) * HW + t0 + tb;
    const float* Xp1 = Xp0 + HW;

    float4 w0 = *(const float4*)Wp;
    float4 w1 = *(const float4*)(Wp + 4);
    float4 x0 = *(const float4*)Xp0;
    float4 x1 = *(const float4*)Xp1;

    float acc[2][8][4];
    #pragma unroll
    for (int i = 0; i < 2; i++)
        #pragma unroll
        for (int j = 0; j < 8; j++)
            #pragma unroll
            for (int r = 0; r < 4; r++) acc[i][j][r] = 0.f;

    const int swr = ((row_w >> 2) & 1) << 2;    // W store swizzle
    const int cp0 = cb >> 1;                    // 0 or 4
    const int swa = ((g >> 2) & 1) << 2;        // A-frag swizzle (row bit2 = g bit2)
    const int xsw = (cp_x & 3) << 3;            // X store swizzle

    int buf = 0;
    for (int k0 = 0; k0 < C; k0 += 16) {
        // ---- convert + store current tile ----
        if (FUSE_GN) {
            const float aa0 = sA[k0 + 2 * cp_x],     bb0 = sB[k0 + 2 * cp_x];
            const float aa1 = sA[k0 + 2 * cp_x + 1], bb1 = sB[k0 + 2 * cp_x + 1];
            x0.x = fmaf(x0.x, aa0, bb0); x0.y = fmaf(x0.y, aa0, bb0);
            x0.z = fmaf(x0.z, aa0, bb0); x0.w = fmaf(x0.w, aa0, bb0);
            x1.x = fmaf(x1.x, aa1, bb1); x1.y = fmaf(x1.y, aa1, bb1);
            x1.z = fmaf(x1.z, aa1, bb1); x1.w = fmaf(x1.w, aa1, bb1);
        }
        {
            uint2 wlo = make_uint2(cvt_f16x2(w0.x, w0.y), cvt_f16x2(w0.z, w0.w));
            uint2 whi = make_uint2(cvt_f16x2(w1.x, w1.y), cvt_f16x2(w1.z, w1.w));
            *(uint2*)&Wt[buf][row_w][cp0 ^ swr]       = wlo;
            *(uint2*)&Wt[buf][row_w][(cp0 + 2) ^ swr] = whi;
            uint4 xu;
            xu.x = cvt_f16x2(x0.x, x1.x);
            xu.y = cvt_f16x2(x0.y, x1.y);
            xu.z = cvt_f16x2(x0.z, x1.z);
            xu.w = cvt_f16x2(x0.w, x1.w);
            *(uint4*)&Xt[buf][cp_x][tb ^ xsw] = xu;
        }
        // ---- prefetch next tile ----
        if (k0 + 16 < C) {
            w0 = *(const float4*)(Wp + k0 + 16);
            w1 = *(const float4*)(Wp + k0 + 20);
            x0 = *(const float4*)(Xp0 + (size_t)(k0 + 16) * HW);
            x1 = *(const float4*)(Xp1 + (size_t)(k0 + 16) * HW);
        }
        __syncthreads();

        // ---- compute on current buffer ----
        uint A[2][4];
        #pragma unroll
        for (int i = 0; i < 2; i++) {
            const uint* wr0 = Wt[buf][wm + i * 16 + g];
            const uint* wr1 = Wt[buf][wm + i * 16 + 8 + g];
            A[i][0] = wr0[tq ^ swa];
            A[i][1] = wr1[tq ^ swa];
            A[i][2] = wr0[(4 + tq) ^ swa];
            A[i][3] = wr1[(4 + tq) ^ swa];
        }
        uint Bf[8][2];
        #pragma unroll
        for (int j = 0; j < 8; j++) {
            const int col = (wn + j * 8 + g) ^ (tq << 3);
            Bf[j][0] = Xt[buf][tq][col];
            Bf[j][1] = Xt[buf][4 + tq][col];
        }
        #pragma unroll
        for (int i = 0; i < 2; i++)
            #pragma unroll
            for (int j = 0; j < 8; j++)
                mma16816(acc[i][j][0], acc[i][j][1], acc[i][j][2], acc[i][j][3],
                         A[i][0], A[i][1], A[i][2], A[i][3],
                         Bf[j][0], Bf[j][1],
                         acc[i][j][0], acc[i][j][1], acc[i][j][2], acc[i][j][3]);
        buf ^= 1;
    }

    // ---- epilogue ----
    #pragma unroll
    for (int i = 0; i < 2; i++) {
        const int r0 = o0 + wm + i * 16 + g;
        const int r1 = r0 + 8;
        const float bv0 = bias[r0];
        const float bv1 = bias[r1];
        #pragma unroll
        for (int j = 0; j < 8; j++) {
            const int col = t0 + wn + j * 8 + 2 * tq;
            const size_t idx0 = ((size_t)n * M + r0) * HW + col;
            const size_t idx1 = ((size_t)n * M + r1) * HW + col;
            float2 v0 = make_float2(acc[i][j][0] + bv0, acc[i][j][1] + bv0);
            float2 v1 = make_float2(acc[i][j][2] + bv1, acc[i][j][3] + bv1);
            if (RESID) {
                const float2 r0v = *(const float2*)(resid + idx0);
                const float2 r1v = *(const float2*)(resid + idx1);
                v0.x += r0v.x; v0.y += r0v.y;
                v1.x += r1v.x; v1.y += r1v.y;
            }
            *(float2*)(Out + idx0) = v0;
            *(float2*)(Out + idx1) = v1;
        }
    }
}

// ---------------------------------------------------------------------------
// Kernel 3: fused attention v6 — fp16 tensor cores (unchanged from R6, WIN).
// ---------------------------------------------------------------------------
__global__ void __launch_bounds__(256, 2)
attn_kernel(const float* __restrict__ qkv, float* __restrict__ y)
{
    __shared__ uint Kh[4096];   // [j][key^(j<<3)]  j = d-pair
    __shared__ uint Vs[4096];   // [d][kp^(d<<2)]   kp = key-pair

    const int b = blockIdx.x;        // n*32 + h
    const int h = b & 31;
    const int n = b >> 5;
    const int tid = threadIdx.x;
    const int warp = tid >> 5, lane = tid & 31;
    const int g = lane >> 2, t = lane & 3;

    const float* qbase = qkv + ((size_t)n * 3 * C + h * HD) * HW;
    const float* kbase = qbase + (size_t)C * HW;
    const float* vbase = qbase + (size_t)2 * C * HW;

    for (int idx = tid; idx < 4096; idx += 256) {
        const int j = idx >> 10, key = idx & 1023;
        __half2 hh = __floats2half2_rn(kbase[(2 * j) * HW + key],
                                       kbase[(2 * j + 1) * HW + key]);
        Kh[(j << 10) | (key ^ (j << 3))] = *(uint*)&hh;
    }
    for (int idx = tid; idx < 4096; idx += 256) {
        const int d = idx >> 9, kp = idx & 511;
        const float2 v2 = *(const float2*)(vbase + (size_t)d * HW + 2 * kp);
        __half2 hh = __floats2half2_rn(v2.x, v2.y);
        Vs[(d << 9) | (kp ^ (d << 2))] = *(uint*)&hh;
    }
    __syncthreads();

    const float qscale = 0.35355339059327373f * 1.4426950408889634f;

    uint qa0[8], qa1[8];
    #pragma unroll
    for (int s = 0; s < 8; s++) {
        const int q0 = (warp + 8 * s) << 4;
        const float* qd0 = qbase + (2 * t) * HW;
        const float* qd1 = qbase + (2 * t + 1) * HW;
        qa0[s] = cvt_f16x2(qd0[q0 + g] * qscale,     qd1[q0 + g] * qscale);
        qa1[s] = cvt_f16x2(qd0[q0 + 8 + g] * qscale, qd1[q0 + 8 + g] * qscale);
    }

    float pv[8][4];
    float l0[8], l1[8];
    #pragma unroll
    for (int s = 0; s < 8; s++) {
        pv[s][0] = pv[s][1] = pv[s][2] = pv[s][3] = 0.f;
        l0[s] = l1[s] = 0.f;
    }

    const uint zero = 0u;

    #pragma unroll 1
    for (int kb = 0; kb < 64; kb++) {
        const int key0 = kb << 4;
        const uint kf0 = Kh[(t << 10) | ((key0 + g) ^ (t << 3))];
        const uint kf1 = Kh[(t << 10) | ((key0 + 8 + g) ^ (t << 3))];
        const int kp0 = kb << 3;
        const uint vf0 = Vs[(g << 9) | ((kp0 + t) ^ (g << 2))];
        const uint vf1 = Vs[(g << 9) | ((kp0 + 4 + t) ^ (g << 2))];

        #pragma unroll
        for (int s = 0; s < 8; s++) {
            float c0, c1, c2, c3, d0, d1, d2, d3;
            mma16816(c0, c1, c2, c3, qa0[s], qa1[s], zero, zero, kf0, zero,
                     0.f, 0.f, 0.f, 0.f);
            mma16816(d0, d1, d2, d3, qa0[s], qa1[s], zero, zero, kf1, zero,
                     0.f, 0.f, 0.f, 0.f);
            const uint pa0 = ex2_f16x2(cvt_f16x2(c0, c1));
            const uint pa1 = ex2_f16x2(cvt_f16x2(c2, c3));
            const uint pa2 = ex2_f16x2(cvt_f16x2(d0, d1));
            const uint pa3 = ex2_f16x2(cvt_f16x2(d2, d3));
            l0[s] += sum_h2(pa0) + sum_h2(pa2);
            l1[s] += sum_h2(pa1) + sum_h2(pa3);
            mma16816(pv[s][0], pv[s][1], pv[s][2], pv[s][3],
                     pa0, pa1, pa2, pa3, vf0, vf1,
                     pv[s][0], pv[s][1], pv[s][2], pv[s][3]);
        }
    }

    float* yb = y + ((size_t)n * C + h * HD) * HW;
    #pragma unroll
    for (int s = 0; s < 8; s++) {
        float la = l0[s], lb = l1[s];
        la += __shfl_xor_sync(0xffffffffu, la, 1);
        la += __shfl_xor_sync(0xffffffffu, la, 2);
        lb += __shfl_xor_sync(0xffffffffu, lb, 1);
        lb += __shfl_xor_sync(0xffffffffu, lb, 2);
        const float inva = __fdividef(1.0f, la);
        const float invb = __fdividef(1.0f, lb);
        const int q0 = (warp + 8 * s) << 4;
        yb[(2 * t) * HW + q0 + g]         = pv[s][0] * inva;
        yb[(2 * t + 1) * HW + q0 + g]     = pv[s][1] * inva;
        yb[(2 * t) * HW + q0 + 8 + g]     = pv[s][2] * invb;
        yb[(2 * t + 1) * HW + q0 + 8 + g] = pv[s][3] * invb;
    }
}

// ---------------------------------------------------------------------------
extern "C" void kernel_launch(void* const* d_in, const int* in_sizes, int n_in,
                              void* d_out, int out_size)
{
    const float* x     = (const float*)d_in[0];
    const float* gn_w  = (const float*)d_in[1];
    const float* gn_b  = (const float*)d_in[2];
    const float* qkv_w = (const float*)d_in[3];
    const float* qkv_b = (const float*)d_in[4];
    const float* out_w = (const float*)d_in[5];
    const float* out_b = (const float*)d_in[6];
    float* out = (float*)d_out;

    float *qkv, *y, *A, *B;
    cudaGetSymbolAddress((void**)&qkv, g_qkv);
    cudaGetSymbolAddress((void**)&y,   g_y);
    cudaGetSymbolAddress((void**)&A,   g_A);
    cudaGetSymbolAddress((void**)&B,   g_B);

    // 1. GroupNorm stats -> per-(n,c) affine
    gn_stats_kernel<<<NB * NG, 256>>>(x, gn_w, gn_b, A, B);

    // 2. QKV projection (fp16 mma) with fused GN affine on X conversion
    {
        dim3 grid(NB, (3 * C) / 128, HW / 128);
        gemm_h_kernel<true, false><<<grid, 256>>>(qkv_w, x, qkv_b, nullptr, A, B, qkv, 3 * C);
    }

    // 3. Attention: 256 CTAs (1 per (n,h)), tensor-core path
    attn_kernel<<<NB * NH, 256>>>(qkv, y);

    // 4. Output projection (fp16 mma) + bias + residual
    {
        dim3 grid(NB, C / 128, HW / 128);
        gemm_h_kernel<false, true><<<grid, 256>>>(out_w, y, out_b, x, nullptr, nullptr, out, C);
    }
}